// round 6
// baseline (speedup 1.0000x reference)
#include <cuda_runtime.h>
#include <cuda_bf16.h>

// CorrelationLayer: out[b,d,h,w] = (1/sqrt(C)) * sum_c x1[b,c,h,w] * x2pad[b,c,h+di,w+dj]
// 80 displacements. B=8, C=128, H=128, W=192, fp32.
// v6: 8 px/thread (TX=8, PH=4), even/odd float4-group interleaved smem layout
//     for conflict-free LDS.128, scalar FFMA, CHS=4 double-buffered cp.async.

#define CC   128
#define HH   128
#define WW   192
#define BB   8
#define PW   64
#define PH   4
#define CHS  4
#define TX   8     // threads along x, 8 px each
#define NDI  9
#define NTHREADS (TX * NDI * PH)         // 288
#define NSTAGES  (CC / CHS)              // 32
#define HALO_H   (PH + 8)                // 12
#define HALO_W   72                      // 18 float4 groups: [e0..e8 | o0..o8]
#define S1_FLT   (CHS * PH * PW)         // 1024
#define S2_FLT   (CHS * HALO_H * HALO_W) // 3456
#define X2_SLOTS 3                       // 864 f4 / 288 thr

__device__ __forceinline__ unsigned smem_u32(const void* p) {
    return (unsigned)__cvta_generic_to_shared(p);
}
__device__ __forceinline__ void cp16(unsigned dst, const char* base, unsigned off) {
    asm volatile("cp.async.cg.shared.global [%0], [%1], 16;\n"
                 :: "r"(dst), "l"(base + off));
}
__device__ __forceinline__ void cp_commit() {
    asm volatile("cp.async.commit_group;\n" ::: "memory");
}
template <int N> __device__ __forceinline__ void cp_wait() {
    asm volatile("cp.async.wait_group %0;\n" :: "n"(N) : "memory");
}

__global__ __launch_bounds__(NTHREADS, 2)
void corr_kernel(const float* __restrict__ x1,
                 const float* __restrict__ x2,
                 float* __restrict__ out)
{
    // s1 row layout (16 groups): [e0..e7 | o0..o7]; s2 row (18): [e0..e8 | o0..o8]
    __shared__ __align__(16) float s1[2][CHS][PH][PW];
    __shared__ __align__(16) float s2[2][CHS][HALO_H][HALO_W];

    const int tid = threadIdx.x;          // 0..287
    const int tx  = tid & 7;              // 0..7  (low bits -> phase lanes share row)
    const int cmb = tid >> 3;             // 0..35
    const int diI = cmb % 9;
    const int pz  = cmb / 9;              // 0..3

    const int w0 = blockIdx.x * PW;
    const int h0 = blockIdx.y * PH;
    const int b  = blockIdx.z;

    // Zero both s2 buffers once: OOB halo entries stay 0 forever.
    {
        float4 z = make_float4(0.f, 0.f, 0.f, 0.f);
        float4* p = (float4*)&s2[0][0][0][0];
        for (int i = tid; i < 2 * S2_FLT / 4; i += NTHREADS) p[i] = z;
    }

    const char* base1 = (const char*)x1;
    const char* base2 = (const char*)x2;

    // ---- x1 slot: 256 f4 over 288 threads (tid < 256), permuted even/odd ----
    unsigned g1off = 0, s1off = 0;
    const bool has1 = (tid < 256);
    if (has1) {
        int ch = tid >> 6, rem = tid & 63;
        int r = rem >> 4, g = rem & 15;
        int pos = (g & 1) ? 8 + (g >> 1) : (g >> 1);
        g1off = (unsigned)((((b * CC + ch) * HH + (h0 + r)) * WW + w0 + 4 * g) * 4);
        s1off = smem_u32(&s1[0][ch][r][4 * pos]);
    }
    // ---- x2 slots: 864 f4 / 288 thr = 3, permuted even/odd ----
    unsigned g2off[X2_SLOTS], s2off[X2_SLOTS];
    bool     pr[X2_SLOTS];
    #pragma unroll
    for (int sl = 0; sl < X2_SLOTS; sl++) {
        int i   = tid + NTHREADS * sl;
        int ch  = i / 216;                // 216 f4 per channel (12 rows * 18)
        int rem = i - ch * 216;
        int r   = rem / 18;
        int g   = rem - r * 18;
        int pos = (g & 1) ? 9 + (g >> 1) : (g >> 1);
        int hr  = h0 - 4 + r;
        int wc  = w0 - 4 + 4 * g;
        pr[sl] = (hr >= 0) && (hr < HH) && (wc >= 0) && (wc < WW);
        int hrc = pr[sl] ? hr : 0;
        int wcc = pr[sl] ? wc : 0;
        g2off[sl] = (unsigned)((((b * CC + ch) * HH + hrc) * WW + wcc) * 4);
        s2off[sl] = smem_u32(&s2[0][ch][r][4 * pos]);
    }

    const unsigned gstep = (unsigned)(CHS * HH * WW * 4);

    float acc[9][8];
    #pragma unroll
    for (int j = 0; j < 9; j++)
        #pragma unroll
        for (int k = 0; k < 8; k++) acc[j][k] = 0.0f;

    const int r2 = pz + diI;              // 0..11

    __syncthreads();   // s2 zero-init visible before first cp.async

    // ---- prologue: stage 0 -> buffer 0 ----
    if (has1) cp16(s1off, base1, g1off);
    #pragma unroll
    for (int sl = 0; sl < X2_SLOTS; sl++)
        if (pr[sl]) cp16(s2off[sl], base2, g2off[sl]);
    cp_commit();

    #pragma unroll 1
    for (int st = 0; st < NSTAGES; st++) {
        const int bb = st & 1;

        cp_wait<0>();
        __syncthreads();    // stage-st data landed AND stage st-1 consumed

        if (st + 1 < NSTAGES) {
            const unsigned bofs1 = (bb ^ 1) * (S1_FLT * 4);
            const unsigned bofs2 = (bb ^ 1) * (S2_FLT * 4);
            if (has1) { g1off += gstep; cp16(s1off + bofs1, base1, g1off); }
            #pragma unroll
            for (int sl = 0; sl < X2_SLOTS; sl++) {
                g2off[sl] += gstep;
                if (pr[sl]) cp16(s2off[sl] + bofs2, base2, g2off[sl]);
            }
            cp_commit();
        }

        #pragma unroll
        for (int ch = 0; ch < CHS; ch++) {
            const float* p1 = &s1[bb][ch][pz][0];
            const float* p2 = &s2[bb][ch][r2][0];
            // x1: even group 2tx (px 8tx..+3), odd group 2tx+1 (px 8tx+4..+7)
            float4 ae = *(const float4*)(p1 + 4 * tx);          // even sec slot tx
            float4 ao = *(const float4*)(p1 + 32 + 4 * tx);     // odd  sec slot tx
            // x2 window floats 8tx..8tx+15:
            float4 e0 = *(const float4*)(p2 + 4 * tx);          // group 2tx
            float4 o0 = *(const float4*)(p2 + 36 + 4 * tx);     // group 2tx+1
            float4 e1 = *(const float4*)(p2 + 4 * tx + 4);      // group 2tx+2
            float4 o1 = *(const float4*)(p2 + 36 + 4 * tx + 4); // group 2tx+3

            float a[8]  = {ae.x, ae.y, ae.z, ae.w, ao.x, ao.y, ao.z, ao.w};
            float v[16] = {e0.x, e0.y, e0.z, e0.w, o0.x, o0.y, o0.z, o0.w,
                           e1.x, e1.y, e1.z, e1.w, o1.x, o1.y, o1.z, o1.w};

            #pragma unroll
            for (int j = 0; j < 9; j++)
                #pragma unroll
                for (int k = 0; k < 8; k++)
                    acc[j][k] = fmaf(a[k], v[j + k], acc[j][k]);
        }
    }

    // ---- epilogue: scale + store (skip center displacement) ----
    const float scale = 0.08838834764831845f;  // 1/sqrt(128)
    const int hh = h0 + pz;
    #pragma unroll
    for (int j = 0; j < 9; j++) {
        int lin = diI * 9 + j;
        if (lin == 40) continue;               // (0,0)
        int d = lin - (lin > 40 ? 1 : 0);
        float* dst = &out[(((size_t)(b * 80 + d) * HH + hh) * WW) + w0 + 8 * tx];
        *(float4*)dst = make_float4(acc[j][0] * scale, acc[j][1] * scale,
                                    acc[j][2] * scale, acc[j][3] * scale);
        *(float4*)(dst + 4) = make_float4(acc[j][4] * scale, acc[j][5] * scale,
                                          acc[j][6] * scale, acc[j][7] * scale);
    }
}

extern "C" void kernel_launch(void* const* d_in, const int* in_sizes, int n_in,
                              void* d_out, int out_size)
{
    const float* x1 = (const float*)d_in[0];
    const float* x2 = (const float*)d_in[1];
    float* out = (float*)d_out;

    dim3 grid(WW / PW, HH / PH, BB);   // (3, 32, 8)
    dim3 block(NTHREADS, 1, 1);        // 288 threads = 9 warps
    corr_kernel<<<grid, block>>>(x1, x2, out);
}

// round 7
// speedup vs baseline: 1.0856x; 1.0856x over previous
#include <cuda_runtime.h>
#include <cuda_bf16.h>

// CorrelationLayer: out[b,d,h,w] = (1/sqrt(C)) * sum_c x1[b,c,h,w] * x2pad[b,c,h+di,w+dj]
// 80 displacements. B=8, C=128, H=128, W=192, fp32.
// v7: 8 px/thread (TX=8, PH=4) with even/odd interleaved smem rows (conflict-free
//     LDS.128), but back to CHS=8 / 16-stage cadence (R6 failed on 32-stage cadence).

#define CC   128
#define HH   128
#define WW   192
#define BB   8
#define PW   64
#define PH   4
#define CHS  8
#define TX   8     // threads along x, 8 px each
#define NDI  9
#define NTHREADS (TX * NDI * PH)         // 288
#define NSTAGES  (CC / CHS)              // 16
#define HALO_H   (PH + 8)                // 12
#define HALO_W   72                      // 18 f4 groups/row: [e0..e8 | o0..o8]
#define S1_FLT   (CHS * PH * PW)         // 2048
#define S2_FLT   (CHS * HALO_H * HALO_W) // 6912
#define S1_F4    (S1_FLT / 4)            // 512
#define S2_F4    (S2_FLT / 4)            // 1728
#define X2_SLOTS 6                       // 1728 / 288

__device__ __forceinline__ unsigned smem_u32(const void* p) {
    return (unsigned)__cvta_generic_to_shared(p);
}
__device__ __forceinline__ void cp16(unsigned dst, const char* base, unsigned off) {
    asm volatile("cp.async.cg.shared.global [%0], [%1], 16;\n"
                 :: "r"(dst), "l"(base + off));
}
__device__ __forceinline__ void cp_commit() {
    asm volatile("cp.async.commit_group;\n" ::: "memory");
}
template <int N> __device__ __forceinline__ void cp_wait() {
    asm volatile("cp.async.wait_group %0;\n" :: "n"(N) : "memory");
}

__global__ __launch_bounds__(NTHREADS, 2)
void corr_kernel(const float* __restrict__ x1,
                 const float* __restrict__ x2,
                 float* __restrict__ out)
{
    // s1 row (16 groups): [e0..e7 | o0..o7]; s2 row (18 groups): [e0..e8 | o0..o8]
    __shared__ __align__(16) float s1[2][CHS][PH][PW];        // 16 KB
    __shared__ __align__(16) float s2[2][CHS][HALO_H][HALO_W];// 55.3 KB

    const int tid = threadIdx.x;          // 0..287
    const int tx  = tid & 7;              // 0..7 (quarter-warp lanes -> contiguous)
    const int cmb = tid >> 3;             // 0..35
    const int diI = cmb % 9;
    const int pz  = cmb / 9;              // 0..3

    const int w0 = blockIdx.x * PW;
    const int h0 = blockIdx.y * PH;
    const int b  = blockIdx.z;

    // Zero both s2 buffers once: OOB halo entries stay 0 forever.
    {
        float4 z = make_float4(0.f, 0.f, 0.f, 0.f);
        float4* p = (float4*)&s2[0][0][0][0];
        for (int i = tid; i < 2 * S2_F4; i += NTHREADS) p[i] = z;
    }

    const char* base1 = (const char*)x1;
    const char* base2 = (const char*)x2;

    // ---- x1 slots: 512 f4 over 288 threads -> 2 slots, even/odd permuted ----
    unsigned g1off[2], s1off[2];
    bool     h1[2];
    #pragma unroll
    for (int sl = 0; sl < 2; sl++) {
        int i = tid + NTHREADS * sl;
        h1[sl] = (i < S1_F4);
        int ii = h1[sl] ? i : 0;
        int ch = ii >> 6, rem = ii & 63;        // 64 f4/channel (4 rows x 16 groups)
        int r = rem >> 4, g = rem & 15;
        int pos = (g & 1) ? 8 + (g >> 1) : (g >> 1);
        g1off[sl] = (unsigned)((((b * CC + ch) * HH + (h0 + r)) * WW + w0 + 4 * g) * 4);
        s1off[sl] = smem_u32(&s1[0][ch][r][4 * pos]);
    }
    // ---- x2 slots: 1728 f4 / 288 thr = 6, even/odd permuted ----
    unsigned g2off[X2_SLOTS], s2off[X2_SLOTS];
    bool     pr[X2_SLOTS];
    #pragma unroll
    for (int sl = 0; sl < X2_SLOTS; sl++) {
        int i   = tid + NTHREADS * sl;
        int ch  = i / 216;                 // 216 f4/channel (12 rows x 18 groups)
        int rem = i - ch * 216;
        int r   = rem / 18;
        int g   = rem - r * 18;
        int pos = (g & 1) ? 9 + (g >> 1) : (g >> 1);
        int hr  = h0 - 4 + r;
        int wc  = w0 - 4 + 4 * g;
        pr[sl] = (hr >= 0) && (hr < HH) && (wc >= 0) && (wc < WW);
        int hrc = pr[sl] ? hr : 0;
        int wcc = pr[sl] ? wc : 0;
        g2off[sl] = (unsigned)((((b * CC + ch) * HH + hrc) * WW + wcc) * 4);
        s2off[sl] = smem_u32(&s2[0][ch][r][4 * pos]);
    }

    const unsigned gstep = (unsigned)(CHS * HH * WW * 4);

    float acc[9][8];
    #pragma unroll
    for (int j = 0; j < 9; j++)
        #pragma unroll
        for (int k = 0; k < 8; k++) acc[j][k] = 0.0f;

    const int r2 = pz + diI;              // 0..11

    __syncthreads();   // s2 zero-init visible before first cp.async

    // ---- prologue: stage 0 -> buffer 0 ----
    #pragma unroll
    for (int sl = 0; sl < 2; sl++) if (h1[sl]) cp16(s1off[sl], base1, g1off[sl]);
    #pragma unroll
    for (int sl = 0; sl < X2_SLOTS; sl++)
        if (pr[sl]) cp16(s2off[sl], base2, g2off[sl]);
    cp_commit();

    #pragma unroll 1
    for (int st = 0; st < NSTAGES; st++) {
        const int bb = st & 1;

        cp_wait<0>();
        __syncthreads();    // stage-st data landed AND stage st-1 consumed

        if (st + 1 < NSTAGES) {
            const unsigned bofs1 = (bb ^ 1) * (S1_FLT * 4);
            const unsigned bofs2 = (bb ^ 1) * (S2_FLT * 4);
            #pragma unroll
            for (int sl = 0; sl < 2; sl++) {
                g1off[sl] += gstep;
                if (h1[sl]) cp16(s1off[sl] + bofs1, base1, g1off[sl]);
            }
            #pragma unroll
            for (int sl = 0; sl < X2_SLOTS; sl++) {
                g2off[sl] += gstep;
                if (pr[sl]) cp16(s2off[sl] + bofs2, base2, g2off[sl]);
            }
            cp_commit();
        }

        #pragma unroll
        for (int ch = 0; ch < CHS; ch++) {
            const float* p1 = &s1[bb][ch][pz][0];
            const float* p2 = &s2[bb][ch][r2][0];
            // x1 pixels 8tx..8tx+7 via even/odd sections
            float4 ae = *(const float4*)(p1 + 4 * tx);           // group 2tx
            float4 ao = *(const float4*)(p1 + 32 + 4 * tx);      // group 2tx+1
            // x2 window floats 8tx..8tx+15
            float4 e0 = *(const float4*)(p2 + 4 * tx);           // group 2tx
            float4 o0 = *(const float4*)(p2 + 36 + 4 * tx);      // group 2tx+1
            float4 e1 = *(const float4*)(p2 + 4 * tx + 4);       // group 2tx+2
            float4 o1 = *(const float4*)(p2 + 36 + 4 * tx + 4);  // group 2tx+3

            float a[8]  = {ae.x, ae.y, ae.z, ae.w, ao.x, ao.y, ao.z, ao.w};
            float v[16] = {e0.x, e0.y, e0.z, e0.w, o0.x, o0.y, o0.z, o0.w,
                           e1.x, e1.y, e1.z, e1.w, o1.x, o1.y, o1.z, o1.w};

            #pragma unroll
            for (int j = 0; j < 9; j++)
                #pragma unroll
                for (int k = 0; k < 8; k++)
                    acc[j][k] = fmaf(a[k], v[j + k], acc[j][k]);
        }
    }

    // ---- epilogue: scale + store (skip center displacement) ----
    const float scale = 0.08838834764831845f;  // 1/sqrt(128)
    const int hh = h0 + pz;
    #pragma unroll
    for (int j = 0; j < 9; j++) {
        int lin = diI * 9 + j;
        if (lin == 40) continue;               // (0,0)
        int d = lin - (lin > 40 ? 1 : 0);
        float* dst = &out[(((size_t)(b * 80 + d) * HH + hh) * WW) + w0 + 8 * tx];
        *(float4*)dst = make_float4(acc[j][0] * scale, acc[j][1] * scale,
                                    acc[j][2] * scale, acc[j][3] * scale);
        *(float4*)(dst + 4) = make_float4(acc[j][4] * scale, acc[j][5] * scale,
                                          acc[j][6] * scale, acc[j][7] * scale);
    }
}

extern "C" void kernel_launch(void* const* d_in, const int* in_sizes, int n_in,
                              void* d_out, int out_size)
{
    const float* x1 = (const float*)d_in[0];
    const float* x2 = (const float*)d_in[1];
    float* out = (float*)d_out;

    dim3 grid(WW / PW, HH / PH, BB);   // (3, 32, 8) = 768 blocks
    dim3 block(NTHREADS, 1, 1);        // 288 threads = 9 warps
    corr_kernel<<<grid, block>>>(x1, x2, out);
}

// round 8
// speedup vs baseline: 1.6369x; 1.5078x over previous
#include <cuda_runtime.h>
#include <cuda_bf16.h>

// CorrelationLayer: out[b,d,h,w] = (1/sqrt(C)) * sum_c x1[b,c,h,w] * x2pad[b,c,h+di,w+dj]
// 80 displacements. B=8, C=128, H=128, W=192, fp32.
// v8: R5 compute core (4 px/thread, 36 acc, diagonal warp pairing) +
//     persistent blocks with atomic ticket scheduling + continuous cp.async
//     pipeline across tiles (epilogue overlaps next tile's loads).

#define CC   128
#define HH   128
#define WW   192
#define PW   64
#define PH   2
#define CHS  8
#define TX   16
#define NDI  9
#define NTHREADS 288
#define NSTAGES  16
#define HALO_H   10
#define HALO_W   72
#define S1_FLT   (CHS * PH * PW)          // 1024
#define S2_FLT   (CHS * HALO_H * HALO_W)  // 5760
#define X2_SLOTS 5
#define NTILES   (3 * 64 * 8)             // 1536
#define NBLK     444                      // 148 SMs * 3 blocks
#define GSTEP    ((unsigned)(CHS * HH * WW * 4))

__device__ unsigned g_ticket;
__global__ void reset_ticket() { g_ticket = NBLK; }

__device__ __forceinline__ unsigned smem_u32(const void* p) {
    return (unsigned)__cvta_generic_to_shared(p);
}
__device__ __forceinline__ void cp16(unsigned dst, const char* base, unsigned off) {
    asm volatile("cp.async.cg.shared.global [%0], [%1], 16;\n"
                 :: "r"(dst), "l"(base + off));
}
__device__ __forceinline__ void sts_zero16(unsigned dst) {
    asm volatile("st.shared.v4.u32 [%0], {%1,%1,%1,%1};\n" :: "r"(dst), "r"(0u));
}
__device__ __forceinline__ void cp_commit() {
    asm volatile("cp.async.commit_group;\n" ::: "memory");
}
template <int N> __device__ __forceinline__ void cp_wait() {
    asm volatile("cp.async.wait_group %0;\n" :: "n"(N) : "memory");
}

__global__ __launch_bounds__(NTHREADS, 3)
void corr_kernel(const float* __restrict__ x1,
                 const float* __restrict__ x2,
                 float* __restrict__ out)
{
    __shared__ __align__(16) float s1[2][CHS][PH][PW];
    __shared__ __align__(16) float s2[2][CHS][HALO_H][HALO_W];
    __shared__ unsigned s_next;

    const int tid = threadIdx.x;
    const int tx  = tid & 15;
    const int hs  = (tid >> 4) & 1;
    const int w   = tid >> 5;
    const int pz  = hs;                      // diagonal pairing (R5)
    const int diI = hs ? (w + 8) % 9 : w;
    const int r2  = pz + diI;

    const char* base1 = (const char*)x1;
    const char* base2 = (const char*)x2;

    // ---- fixed smem slot addresses (buffer 0) ----
    const bool has1 = (tid < 256);
    unsigned s1off = 0;
    if (has1) {
        int ch = tid >> 5, r = (tid >> 4) & 1, c4 = tid & 15;
        s1off = smem_u32(&s1[0][ch][r][4 * c4]);
    }
    unsigned s2off[X2_SLOTS];
    #pragma unroll
    for (int sl = 0; sl < X2_SLOTS; sl++) {
        int i   = tid + NTHREADS * sl;
        int ch  = i / 180;
        int rem = i - ch * 180;
        int rr  = rem / 18;
        int c4  = rem - rr * 18;
        s2off[sl] = smem_u32(&s2[0][ch][rr][4 * c4]);
    }

    // ---- per-tile gmem offsets (recomputed per tile, not per stage) ----
    unsigned g1off = 0;
    unsigned g2off[X2_SLOTS];
    bool     pr[X2_SLOTS];

    auto setup = [&](unsigned t) {
        unsigned wx = t % 3u;
        unsigned q  = t / 3u;
        int w0 = (int)wx * PW;
        int h0 = (int)(q & 63u) * PH;
        int b  = (int)(q >> 6);
        if (has1) {
            int ch = tid >> 5, r = (tid >> 4) & 1, c4 = tid & 15;
            g1off = (unsigned)((((b * CC + ch) * HH + h0 + r) * WW + w0 + 4 * c4) * 4);
        }
        #pragma unroll
        for (int sl = 0; sl < X2_SLOTS; sl++) {
            int i   = tid + NTHREADS * sl;
            int ch  = i / 180;
            int rem = i - ch * 180;
            int rr  = rem / 18;
            int c4  = rem - rr * 18;
            int hr  = h0 - 4 + rr;
            int wc  = w0 - 4 + 4 * c4;
            pr[sl] = (hr >= 0) && (hr < HH) && (wc >= 0) && (wc < WW);
            int hrc = pr[sl] ? hr : 0;
            int wcc = pr[sl] ? wc : 0;
            g2off[sl] = (unsigned)((((b * CC + ch) * HH + hrc) * WW + wcc) * 4);
        }
    };

    auto issue = [&](int buf) {
        const unsigned b1 = (unsigned)buf * (S1_FLT * 4);
        const unsigned b2 = (unsigned)buf * (S2_FLT * 4);
        if (has1) cp16(s1off + b1, base1, g1off);
        #pragma unroll
        for (int sl = 0; sl < X2_SLOTS; sl++) {
            if (pr[sl]) cp16(s2off[sl] + b2, base2, g2off[sl]);
            else        sts_zero16(s2off[sl] + b2);
        }
        cp_commit();
    };

    float acc[9][4];
    #pragma unroll
    for (int j = 0; j < 9; j++)
        #pragma unroll
        for (int k = 0; k < 4; k++) acc[j][k] = 0.0f;

    unsigned t = blockIdx.x;
    setup(t);
    issue(0);
    unsigned gs = 0;     // global stage counter (buffer = gs & 1)

    const float scale = 0.08838834764831845f;   // 1/sqrt(128)

    for (;;) {
        // epilogue base for this tile
        unsigned q  = t / 3u;
        unsigned obase = (((q >> 6) * 80u) * HH + ((q & 63u) * PH + pz)) * WW
                       + (t % 3u) * PW + 4 * tx;
        unsigned tnext = NTILES;

        #pragma unroll 1
        for (int st = 0; st < NSTAGES; st++, gs++) {
            const int bb = (int)(gs & 1u);
            cp_wait<0>();
            __syncthreads();

            if (st == 0) {
                if (tid == 0) s_next = atomicAdd(&g_ticket, 1u);
            }
            if (st < NSTAGES - 1) {
                g1off += GSTEP;
                #pragma unroll
                for (int sl = 0; sl < X2_SLOTS; sl++) g2off[sl] += GSTEP;
                issue(bb ^ 1);
            } else {
                tnext = s_next;            // written at st==0; 15 syncs since
                if (tnext < NTILES) { setup(tnext); issue(bb ^ 1); }
            }

            const float* p1 = &s1[bb][0][pz][4 * tx];
            const float* p2 = &s2[bb][0][r2][4 * tx];
            #pragma unroll
            for (int ch = 0; ch < CHS; ch++) {
                float4 a4 = *(const float4*)(p1 + ch * (PH * PW));
                float4 t0 = *(const float4*)(p2 + ch * (HALO_H * HALO_W));
                float4 t1 = *(const float4*)(p2 + ch * (HALO_H * HALO_W) + 4);
                float4 t2 = *(const float4*)(p2 + ch * (HALO_H * HALO_W) + 8);
                float a[4]  = {a4.x, a4.y, a4.z, a4.w};
                float v[12] = {t0.x, t0.y, t0.z, t0.w,
                               t1.x, t1.y, t1.z, t1.w,
                               t2.x, t2.y, t2.z, t2.w};
                #pragma unroll
                for (int j = 0; j < 9; j++)
                    #pragma unroll
                    for (int k = 0; k < 4; k++)
                        acc[j][k] = fmaf(a[k], v[j + k], acc[j][k]);
            }
        }

        // ---- epilogue (overlaps the already-issued next-tile loads) ----
        #pragma unroll
        for (int j = 0; j < 9; j++) {
            int lin = diI * 9 + j;
            if (lin == 40) continue;               // (0,0) displacement
            int d = lin - (lin > 40 ? 1 : 0);
            float4 o;
            o.x = acc[j][0] * scale;
            o.y = acc[j][1] * scale;
            o.z = acc[j][2] * scale;
            o.w = acc[j][3] * scale;
            *(float4*)&out[obase + (unsigned)d * (HH * WW)] = o;
        }

        if (tnext >= NTILES) break;
        #pragma unroll
        for (int j = 0; j < 9; j++)
            #pragma unroll
            for (int k = 0; k < 4; k++) acc[j][k] = 0.0f;
        t = tnext;
    }
}

extern "C" void kernel_launch(void* const* d_in, const int* in_sizes, int n_in,
                              void* d_out, int out_size)
{
    const float* x1 = (const float*)d_in[0];
    const float* x2 = (const float*)d_in[1];
    float* out = (float*)d_out;

    reset_ticket<<<1, 1>>>();
    corr_kernel<<<NBLK, NTHREADS>>>(x1, x2, out);
}